// round 14
// baseline (speedup 1.0000x reference)
#include <cuda_runtime.h>
#include <cuda_bf16.h>
#include <cstdint>

#define BATCH   4096
#define FILTER  1024
#define RELC    19
#define RELD    1024
#define SLAB    (FILTER * RELC)        // 19456 floats per batch row
#define HALF    (SLAB / 2)             // 9728 floats (= 512*19)
#define HALF_B  (HALF * 4)             // 38912 bytes
#define NT      608                    // 19 * 32 threads
#define KPC     16                     // f-chunks per thread per half-slab
#define NBUF    2                      // ring depth per CTA (2 CTAs/SM overlap)

// W[f][r] = sum_e U[f,e]*R[r,e], row-major [FILTER][RELC]
__device__ float W_global[SLAB];
// Monotonic grid-barrier counter: never reset, replay-safe.
__device__ unsigned int g_arrive;

// ---------------------------------------------------------------------------
// mbarrier / bulk-copy helpers
// ---------------------------------------------------------------------------
__device__ __forceinline__ void mbar_init(uint32_t mbar, uint32_t count) {
    asm volatile("mbarrier.init.shared.b64 [%0], %1;" :: "r"(mbar), "r"(count) : "memory");
}
__device__ __forceinline__ void mbar_expect_tx(uint32_t mbar, uint32_t bytes) {
    asm volatile("mbarrier.arrive.expect_tx.shared.b64 _, [%0], %1;"
                 :: "r"(mbar), "r"(bytes) : "memory");
}
__device__ __forceinline__ void bulk_g2s(uint32_t dst_smem, const void* src, uint32_t bytes,
                                         uint32_t mbar) {
    asm volatile("cp.async.bulk.shared::cta.global.mbarrier::complete_tx::bytes "
                 "[%0], [%1], %2, [%3];"
                 :: "r"(dst_smem), "l"(src), "r"(bytes), "r"(mbar) : "memory");
}
__device__ __forceinline__ void mbar_wait(uint32_t mbar, uint32_t parity) {
    uint32_t done;
    asm volatile(
        "{\n\t.reg .pred p;\n\t"
        "mbarrier.try_wait.parity.acquire.cta.shared::cta.b64 p, [%1], %2;\n\t"
        "selp.b32 %0, 1, 0, p;\n\t}"
        : "=r"(done) : "r"(mbar), "r"(parity) : "memory");
    if (!done) {
        asm volatile(
            "{\n\t.reg .pred P1;\n\t"
            "W_%=:\n\t"
            "mbarrier.try_wait.parity.acquire.cta.shared::cta.b64 P1, [%0], %1, 0x989680;\n\t"
            "@P1 bra.uni D_%=;\n\t"
            "bra.uni W_%=;\n\t"
            "D_%=:\n\t}"
            :: "r"(mbar), "r"(parity) : "memory");
    }
}

// ---------------------------------------------------------------------------
// Fused persistent kernel, TWO CTAs PER SM (G = 2 * num_SMs).
//   Rationale: single-CTA variants cap at ~80% DRAM because the engine does
//   exactly 2 chunk-copies (~1900 cyc) per ~3400-cyc slab period; the rest of
//   the period (compute/sync/reduce, stall-bound at 19 warps) is DRAM-dead.
//   Two phase-shifted CTAs per SM keep copies in flight through each other's
//   compute phases and double warp-level latency hiding (38 warps/SM).
//   Registers: capped at 53/thread (65536/1216). Phase A is written lean
//   (u reloaded per k, ~35 live regs) so Phase B's w[32]+locals sets the max.
//   Prologue: stage R (76KB = exactly NBUF ring buffers) -> Phase A computes
//   W = U @ R^T from SMEM -> refill ring with conv chunks -> grid barrier ->
//   Phase B 2-deep ring streamer (compile-time w[] indices only).
// Index identity: slab element (tid + 608*k) has r = tid % 19, so per-thread
// work is linear conflict-free smem reads against W registers.
// ---------------------------------------------------------------------------
__global__ void __launch_bounds__(NT, 2)
fused_kernel(const float* __restrict__ conv, const float* __restrict__ U,
             const float* __restrict__ R, float* __restrict__ out)
{
    extern __shared__ float smem[];
    float* red = smem + NBUF * HALF;                         // 2*608 floats
    uint32_t sbase = (uint32_t)__cvta_generic_to_shared(smem);
    uint32_t mb    = sbase + (NBUF * HALF + 2 * NT) * 4;     // 2 ring mbars + 1 R mbar
    uint32_t mb_R  = mb + 8 * NBUF;

    const int tid  = threadIdx.x;
    const int G    = gridDim.x;
    const int b0   = blockIdx.x;
    const int warp = tid >> 5;
    const int lane = tid & 31;

    const int niter = (BATCH - 1 - b0) / G + 1;              // slabs for this block

    // ---- prologue: mbarriers + stage R into the whole ring (2 buffers) ----
    if (tid == 0) {
        #pragma unroll
        for (int i = 0; i <= NBUF; i++) mbar_init(mb + 8 * i, 1);
        asm volatile("fence.proxy.async.shared::cta;" ::: "memory");
        mbar_expect_tx(mb_R, NBUF * HALF_B);
        bulk_g2s(sbase, R, NBUF * HALF_B, mb_R);             // 77824 B = all of R
    }
    __syncthreads();               // mbarrier init visible to all waiters

    // ---- Phase A: W rows, R read from SMEM; lean register usage ----
    mbar_wait(mb_R, 0);            // acquire: R tile visible for LDS
    {
        int f = b0 + G * warp;
        if (f < FILTER) {
            const float4* u4  = reinterpret_cast<const float4*>(U + (size_t)f * RELD);
            const float4* Rs4 = reinterpret_cast<const float4*>(smem);
            float acc[RELC];
            #pragma unroll
            for (int r = 0; r < RELC; r++) acc[r] = 0.f;
            for (int k = 0; k < 8; k++) {                    // NOT unrolled: u not kept live
                float4 uk = __ldg(&u4[lane + 32 * k]);
                #pragma unroll
                for (int r = 0; r < RELC; r++) {
                    float4 rv = Rs4[r * 256 + lane + 32 * k];
                    acc[r] += uk.x * rv.x + uk.y * rv.y + uk.z * rv.z + uk.w * rv.w;
                }
            }
            #pragma unroll
            for (int o = 16; o > 0; o >>= 1)
                #pragma unroll
                for (int r = 0; r < RELC; r++)
                    acc[r] += __shfl_xor_sync(0xFFFFFFFFu, acc[r], o);
            if (lane == 0) {
                #pragma unroll
                for (int r = 0; r < RELC; r++)
                    W_global[f * RELC + r] = acc[r];
            }
        }
    }

    __threadfence();               // publish W rows
    __syncthreads();               // all warps done reading R (ring free)

    // Refill ring with conv chunks 0,1 BEFORE the grid barrier (engine streams
    // through the barrier skew), then arrive/wait on the monotonic barrier.
    if (tid == 0) {
        #pragma unroll
        for (int c = 0; c < NBUF; c++) {
            mbar_expect_tx(mb + 8 * c, HALF_B);
            bulk_g2s(sbase + (uint32_t)c * HALF_B,
                     conv + (size_t)b0 * SLAB + (size_t)c * HALF,
                     HALF_B, mb + 8 * c);
        }
        unsigned int old = atomicAdd(&g_arrive, 1u);
        unsigned int tgt = (old / (unsigned)G + 1u) * (unsigned)G;
        while (*((volatile unsigned int*)&g_arrive) < tgt) __nanosleep(64);
        __threadfence();           // acquire: other blocks' W visible
    }
    __syncthreads();

    // ---- per-thread W slice in registers (compile-time indices ONLY below) ----
    float w[2 * KPC];
    #pragma unroll
    for (int k = 0; k < 2 * KPC; k++) w[k] = W_global[tid + NT * k];

    // ---- Phase B: per-slab loop, 2-deep ring (buffer c == chunk c of slab) ----
    for (int s = 0; s < niter; s++) {
        const uint32_t par = (uint32_t)(s & 1);

        // -- even chunk (buffer 0): w[0..15] --
        mbar_wait(mb, par);
        const float* cb = smem;
        float acc = 0.f;
        #pragma unroll
        for (int k = 0; k < KPC; k++)
            acc = fmaf(cb[tid + NT * k], w[k], acc);

        // -- odd chunk (buffer 1): w[16..31] --
        mbar_wait(mb + 8, par);
        cb = smem + HALF;
        #pragma unroll
        for (int k = 0; k < KPC; k++)
            acc = fmaf(cb[tid + NT * k], w[KPC + k], acc);

        // -- publish partials; ONE sync per slab (red dbl-buffered by s&1) --
        float* rd = red + (s & 1) * NT;
        rd[tid] = acc;
        __syncthreads();           // both buffers free + red visible

        // -- refill both buffers with next slab's chunks --
        if (tid == 0 && s + 1 < niter) {
            const float* src = conv + (size_t)(b0 + (s + 1) * G) * SLAB;
            #pragma unroll
            for (int c = 0; c < NBUF; c++) {
                mbar_expect_tx(mb + 8 * c, HALF_B);
                bulk_g2s(sbase + (uint32_t)c * HALF_B,
                         src + (size_t)c * HALF, HALF_B, mb + 8 * c);
            }
        }

        // -- final 32 -> 1 reduction per r, write scores --
        if (tid < RELC) {
            float sum = 0.f;
            #pragma unroll
            for (int g = 0; g < 32; g++) sum += rd[tid + RELC * g];
            out[(size_t)(b0 + s * G) * RELC + tid] = sum;
        }
    }
}

// ---------------------------------------------------------------------------
// Launch: single fused kernel, 2 CTAs per SM
// ---------------------------------------------------------------------------
extern "C" void kernel_launch(void* const* d_in, const int* in_sizes, int n_in,
                              void* d_out, int out_size)
{
    const float* conv = nullptr;   // 4096*1024*19 = 79691776
    const float* R    = nullptr;   // 19*1024      = 19456
    const float* U    = nullptr;   // 1024*1024    = 1048576
    for (int i = 0; i < n_in; i++) {
        switch (in_sizes[i]) {
            case 79691776: conv = (const float*)d_in[i]; break;
            case 19456:    R    = (const float*)d_in[i]; break;
            case 1048576:  U    = (const float*)d_in[i]; break;
        }
    }
    float* out = (float*)d_out;

    int nsm = 148;
    cudaDeviceGetAttribute(&nsm, cudaDevAttrMultiProcessorCount, 0);

    // 2 ring buffers + dbl-buffered red scratch + 3 mbarriers = ~82.7 KB/CTA
    size_t smem_bytes = (size_t)(NBUF * HALF + 2 * NT) * sizeof(float) + (NBUF + 1) * 8;
    cudaFuncSetAttribute(fused_kernel, cudaFuncAttributeMaxDynamicSharedMemorySize,
                         (int)smem_bytes);
    fused_kernel<<<2 * nsm, NT, smem_bytes>>>(conv, U, R, out);
}

// round 16
// speedup vs baseline: 1.0786x; 1.0786x over previous
#include <cuda_runtime.h>
#include <cuda_bf16.h>
#include <cstdint>

#define BATCH   4096
#define FILTER  1024
#define RELC    19
#define RELD    1024
#define SLAB    (FILTER * RELC)        // 19456 floats per batch row (77824 B)
#define NT      608                    // 19 * 32 threads
#define KPT     32                     // f-chunks per thread per slab
#define SG      4                      // slabs per reduction group

// W[f][r] = sum_e U[f,e]*R[r,e], row-major [FILTER][RELC]
__device__ float W_global[SLAB];
// Monotonic grid-barrier counter: never reset, replay-safe.
__device__ unsigned int g_arrive;

// ---------------------------------------------------------------------------
// mbarrier / bulk-copy helpers (only used to stage R for Phase A)
// ---------------------------------------------------------------------------
__device__ __forceinline__ void mbar_init(uint32_t mbar, uint32_t count) {
    asm volatile("mbarrier.init.shared.b64 [%0], %1;" :: "r"(mbar), "r"(count) : "memory");
}
__device__ __forceinline__ void mbar_expect_tx(uint32_t mbar, uint32_t bytes) {
    asm volatile("mbarrier.arrive.expect_tx.shared.b64 _, [%0], %1;"
                 :: "r"(mbar), "r"(bytes) : "memory");
}
__device__ __forceinline__ void bulk_g2s(uint32_t dst_smem, const void* src, uint32_t bytes,
                                         uint32_t mbar) {
    asm volatile("cp.async.bulk.shared::cta.global.mbarrier::complete_tx::bytes "
                 "[%0], [%1], %2, [%3];"
                 :: "r"(dst_smem), "l"(src), "r"(bytes), "r"(mbar) : "memory");
}
__device__ __forceinline__ void mbar_wait(uint32_t mbar, uint32_t parity) {
    uint32_t done;
    asm volatile(
        "{\n\t.reg .pred p;\n\t"
        "mbarrier.try_wait.parity.acquire.cta.shared::cta.b64 p, [%1], %2;\n\t"
        "selp.b32 %0, 1, 0, p;\n\t}"
        : "=r"(done) : "r"(mbar), "r"(parity) : "memory");
    if (!done) {
        asm volatile(
            "{\n\t.reg .pred P1;\n\t"
            "W_%=:\n\t"
            "mbarrier.try_wait.parity.acquire.cta.shared::cta.b64 P1, [%0], %1, 0x989680;\n\t"
            "@P1 bra.uni D_%=;\n\t"
            "bra.uni W_%=;\n\t"
            "D_%=:\n\t}"
            :: "r"(mbar), "r"(parity) : "memory");
    }
}
__device__ __forceinline__ void prefetch_l2(const void* p) {
    asm volatile("prefetch.global.L2 [%0];" :: "l"(p));
}

// ---------------------------------------------------------------------------
// Fused persistent kernel, DIRECT-LDG streaming (no conv smem staging).
//   Why: smem-staged variants cap at ~76-80% DRAM because the consumption
//   period (~2513 cyc/slab: bulk smem-write 608 + LDS 608 crossbar cyc +
//   waits/sync/reduce) exceeds the copy time (~1900 cyc), so the engine
//   idles ~600 cyc/slab waiting for free buffers. Direct coalesced __ldcs
//   makes delivery == consumption: the SMs throughput-limit on the memory
//   system itself with no starvation term, no ring, no mbarriers for conv.
//   4 slabs per group = 4 independent accumulator streams (deep MLP, hides
//   DRAM latency + TLB PTW); ONE __syncthreads per 4 slabs (red dbl-buffered).
//   Phase A (W = U @ R^T) unchanged from the best round: R bulk-staged to
//   smem; group-0 conv lines prefetched to L2 so DRAM streams through it.
// Index identity: slab element (tid + 608*k) has r = tid % 19, f = const+32k,
// so per-thread work is linear coalesced gmem reads against W registers.
// ---------------------------------------------------------------------------
__global__ void __launch_bounds__(NT, 1)
fused_kernel(const float* __restrict__ conv, const float* __restrict__ U,
             const float* __restrict__ R, float* __restrict__ out)
{
    extern __shared__ float smem[];                    // 77824 B: R tile, later red
    uint32_t sbase = (uint32_t)__cvta_generic_to_shared(smem);
    uint32_t mb_R  = sbase + SLAB * 4;                 // 8B-aligned (77824 % 8 == 0)

    const int tid  = threadIdx.x;
    const int G    = gridDim.x;
    const int b0   = blockIdx.x;
    const int warp = tid >> 5;
    const int lane = tid & 31;

    const int niter = (BATCH - 1 - b0) / G + 1;        // slabs for this block

    // ---- stage R into smem (one 76KB bulk copy) ----
    if (tid == 0) {
        mbar_init(mb_R, 1);
        asm volatile("fence.proxy.async.shared::cta;" ::: "memory");
        mbar_expect_tx(mb_R, SLAB * 4);
        bulk_g2s(sbase, R, SLAB * 4, mb_R);
    }
    __syncthreads();

    // ---- L2-prefetch group 0 of conv (1 line per thread per slab) ----
    #pragma unroll
    for (int s = 0; s < SG; s++) {
        int b = b0 + s * G;
        if (b < BATCH)
            prefetch_l2(conv + (size_t)b * SLAB + (size_t)tid * 32);
    }

    // ---- Phase A: W rows, R read from SMEM (one warp per f-row) ----
    mbar_wait(mb_R, 0);
    {
        int f = b0 + G * warp;
        if (f < FILTER) {
            const float4* u4  = reinterpret_cast<const float4*>(U + (size_t)f * RELD);
            const float4* Rs4 = reinterpret_cast<const float4*>(smem);
            float acc[RELC];
            #pragma unroll
            for (int r = 0; r < RELC; r++) acc[r] = 0.f;
            for (int k = 0; k < 8; k++) {              // u not kept live across k
                float4 uk = __ldg(&u4[lane + 32 * k]);
                #pragma unroll
                for (int r = 0; r < RELC; r++) {
                    float4 rv = Rs4[r * 256 + lane + 32 * k];
                    acc[r] += uk.x * rv.x + uk.y * rv.y + uk.z * rv.z + uk.w * rv.w;
                }
            }
            #pragma unroll
            for (int o = 16; o > 0; o >>= 1)
                #pragma unroll
                for (int r = 0; r < RELC; r++)
                    acc[r] += __shfl_xor_sync(0xFFFFFFFFu, acc[r], o);
            if (lane == 0) {
                #pragma unroll
                for (int r = 0; r < RELC; r++)
                    W_global[f * RELC + r] = acc[r];
            }
        }
    }

    __threadfence();               // publish W rows
    __syncthreads();               // block done with R (smem reusable as red)

    // ---- grid barrier (monotonic counter: replay-safe) ----
    if (tid == 0) {
        unsigned int old = atomicAdd(&g_arrive, 1u);
        unsigned int tgt = (old / (unsigned)G + 1u) * (unsigned)G;
        while (*((volatile unsigned int*)&g_arrive) < tgt) __nanosleep(64);
        __threadfence();           // acquire: other blocks' W visible
    }
    __syncthreads();

    // ---- per-thread W slice in registers (compile-time indices only) ----
    float w[KPT];
    #pragma unroll
    for (int k = 0; k < KPT; k++) w[k] = W_global[tid + NT * k];

    // ---- Phase B: direct-LDG streaming, 4 slabs per group ----
    float* red = smem;             // 2 * SG * NT floats = 19456 B (dbl-buffered)
    const int ngroups = (niter + SG - 1) / SG;

    for (int gq = 0; gq < ngroups; gq++) {
        const int sb = gq * SG;    // first block-local slab of this group

        // Clamped base pointers (invalid streams read slab BATCH-1, discarded)
        int bA = b0 + (sb + 0) * G; if (bA > BATCH - 1) bA = BATCH - 1;
        int bB = b0 + (sb + 1) * G; if (bB > BATCH - 1) bB = BATCH - 1;
        int bC = b0 + (sb + 2) * G; if (bC > BATCH - 1) bC = BATCH - 1;
        int bD = b0 + (sb + 3) * G; if (bD > BATCH - 1) bD = BATCH - 1;
        const float* pA = conv + (size_t)bA * SLAB + tid;
        const float* pB = conv + (size_t)bB * SLAB + tid;
        const float* pC = conv + (size_t)bC * SLAB + tid;
        const float* pD = conv + (size_t)bD * SLAB + tid;

        float a0 = 0.f, a1 = 0.f, a2 = 0.f, a3 = 0.f;
        #pragma unroll
        for (int k = 0; k < KPT; k++) {
            a0 = fmaf(__ldcs(pA + NT * k), w[k], a0);
            a1 = fmaf(__ldcs(pB + NT * k), w[k], a1);
            a2 = fmaf(__ldcs(pC + NT * k), w[k], a2);
            a3 = fmaf(__ldcs(pD + NT * k), w[k], a3);
        }

        // publish partials; ONE sync per group (red dbl-buffered by gq&1)
        float* rd = red + (gq & 1) * (SG * NT);
        rd[0 * NT + tid] = a0;
        rd[1 * NT + tid] = a1;
        rd[2 * NT + tid] = a2;
        rd[3 * NT + tid] = a3;
        __syncthreads();

        // 76 threads reduce one (slab, r) each; other 16.25 warps proceed
        // immediately to the next group's loads (no trailing sync needed).
        if (tid < SG * RELC) {
            int s4 = tid / RELC, r = tid % RELC;
            int sl = sb + s4;
            if (sl < niter) {
                const float* rs = rd + s4 * NT;
                float sum = 0.f;
                #pragma unroll
                for (int g = 0; g < 32; g++) sum += rs[r + RELC * g];
                out[(size_t)(b0 + sl * G) * RELC + r] = sum;
            }
        }
    }
}

// ---------------------------------------------------------------------------
// Launch: single fused kernel, 1 CTA per SM (full register budget, no spill)
// ---------------------------------------------------------------------------
extern "C" void kernel_launch(void* const* d_in, const int* in_sizes, int n_in,
                              void* d_out, int out_size)
{
    const float* conv = nullptr;   // 4096*1024*19 = 79691776
    const float* R    = nullptr;   // 19*1024      = 19456
    const float* U    = nullptr;   // 1024*1024    = 1048576
    for (int i = 0; i < n_in; i++) {
        switch (in_sizes[i]) {
            case 79691776: conv = (const float*)d_in[i]; break;
            case 19456:    R    = (const float*)d_in[i]; break;
            case 1048576:  U    = (const float*)d_in[i]; break;
        }
    }
    float* out = (float*)d_out;

    int nsm = 148;
    cudaDeviceGetAttribute(&nsm, cudaDevAttrMultiProcessorCount, 0);

    // R tile (76KB, reused as red scratch) + 1 mbarrier
    size_t smem_bytes = (size_t)SLAB * sizeof(float) + 8;
    cudaFuncSetAttribute(fused_kernel, cudaFuncAttributeMaxDynamicSharedMemorySize,
                         (int)smem_bytes);
    fused_kernel<<<nsm, NT, smem_bytes>>>(conv, U, R, out);
}